// round 4
// baseline (speedup 1.0000x reference)
#include <cuda_runtime.h>

#define N_V   2048
#define N_E   1024
#define N_MOL 64
#define V_DIM 128
#define E_DIM 64
#define Q_DIM 3
#define H_DIM 32
#define FEAT  (2*V_DIM + E_DIM)   // 320

// Scratch (static device globals — allocation-free per harness rules)
__device__ int g_src[N_E];
__device__ int g_dst[N_E];
__device__ int g_mol[N_V];
__device__ int g_sorted[N_V];
__device__ int g_off[N_MOL + 1];

// ---------------------------------------------------------------------------
// Kernel A: recover integer indices from one-hot matrices.
// vew1/vew2: [N_V, N_E] row-major, vew1[i,j]==1 <=> src[j]==i.
// mvw: [N_MOL, N_V] row-major, mvw[g,i]==1 <=> mol[i]==g.
// ---------------------------------------------------------------------------
__global__ void recover_kernel(const float4* __restrict__ vew1,
                               const float4* __restrict__ vew2,
                               const float4* __restrict__ mvw) {
    const int stride = gridDim.x * blockDim.x;
    const int n4 = (N_V * N_E) / 4;           // 524288
    for (int t = blockIdx.x * blockDim.x + threadIdx.x; t < n4; t += stride) {
        float4 a = vew1[t];
        float4 b = vew2[t];
        int i = t >> 8;                       // / (N_E/4)
        int j = (t & 255) << 2;
        if (a.x != 0.f) g_src[j + 0] = i;
        if (a.y != 0.f) g_src[j + 1] = i;
        if (a.z != 0.f) g_src[j + 2] = i;
        if (a.w != 0.f) g_src[j + 3] = i;
        if (b.x != 0.f) g_dst[j + 0] = i;
        if (b.y != 0.f) g_dst[j + 1] = i;
        if (b.z != 0.f) g_dst[j + 2] = i;
        if (b.w != 0.f) g_dst[j + 3] = i;
    }
    const int nm4 = (N_MOL * N_V) / 4;        // 32768
    for (int t = blockIdx.x * blockDim.x + threadIdx.x; t < nm4; t += stride) {
        float4 a = mvw[t];
        int g = t >> 9;                       // / (N_V/4)
        int i = (t & 511) << 2;
        if (a.x != 0.f) g_mol[i + 0] = g;
        if (a.y != 0.f) g_mol[i + 1] = g;
        if (a.z != 0.f) g_mol[i + 2] = g;
        if (a.w != 0.f) g_mol[i + 3] = g;
    }
}

// ---------------------------------------------------------------------------
// Kernel C: deterministic counting sort of vertices by molecule.
// ---------------------------------------------------------------------------
__global__ void group_kernel() {
    __shared__ int cnt[N_MOL];
    __shared__ int soff[N_MOL + 1];
    const int tid = threadIdx.x;
    if (tid < N_MOL) cnt[tid] = 0;
    __syncthreads();
    for (int i = tid; i < N_V; i += blockDim.x)
        atomicAdd(&cnt[g_mol[i]], 1);
    __syncthreads();
    if (tid == 0) {
        int s = 0;
        for (int k = 0; k < N_MOL; k++) { soff[k] = s; s += cnt[k]; }
        soff[N_MOL] = s;
    }
    __syncthreads();
    if (tid <= N_MOL) g_off[tid] = soff[tid];
    if (tid < N_MOL) {
        int p = soff[tid];
        for (int i = 0; i < N_V; i++)
            if (g_mol[i] == tid) g_sorted[p++] = i;
    }
}

// ---------------------------------------------------------------------------
// Kernel B: bond forces. One warp per row k of [2*N_E].
// feat = [v[u], e[er], v[w]]; h = relu(W1 @ feat); val = W2·h + b2;
// out[k] = (q[u]-q[w])/||.|| * val    (writes ALL of d_out)
// float4-vectorized: W1 row per lane is contiguous; v/e rows 16B-aligned.
// ---------------------------------------------------------------------------
__global__ void bond_kernel(const float* __restrict__ v,
                            const float* __restrict__ e,
                            const float* __restrict__ q,
                            const float* __restrict__ W1,
                            const float* __restrict__ W2,
                            const float* __restrict__ b2,
                            float* __restrict__ out) {
    const int warp = (blockIdx.x * blockDim.x + threadIdx.x) >> 5;
    const int lane = threadIdx.x & 31;
    if (warp >= 2 * N_E) return;
    const int er = (warp < N_E) ? warp : warp - N_E;
    int u, w;
    if (warp < N_E) { u = g_src[er]; w = g_dst[er]; }
    else            { u = g_dst[er]; w = g_src[er]; }

    const float4* __restrict__ W1r = (const float4*)(W1 + lane * FEAT);
    const float4* __restrict__ vu  = (const float4*)(v + u * V_DIM);
    const float4* __restrict__ vw  = (const float4*)(v + w * V_DIM);
    const float4* __restrict__ ee  = (const float4*)(e + er * E_DIM);

    float h = 0.f;
    #pragma unroll
    for (int c = 0; c < V_DIM / 4; c++) {
        float4 a = vu[c], b = W1r[c];
        h = fmaf(a.x, b.x, h); h = fmaf(a.y, b.y, h);
        h = fmaf(a.z, b.z, h); h = fmaf(a.w, b.w, h);
    }
    #pragma unroll
    for (int c = 0; c < E_DIM / 4; c++) {
        float4 a = ee[c], b = W1r[V_DIM/4 + c];
        h = fmaf(a.x, b.x, h); h = fmaf(a.y, b.y, h);
        h = fmaf(a.z, b.z, h); h = fmaf(a.w, b.w, h);
    }
    #pragma unroll
    for (int c = 0; c < V_DIM / 4; c++) {
        float4 a = vw[c], b = W1r[(V_DIM + E_DIM)/4 + c];
        h = fmaf(a.x, b.x, h); h = fmaf(a.y, b.y, h);
        h = fmaf(a.z, b.z, h); h = fmaf(a.w, b.w, h);
    }
    h = fmaxf(h, 0.f);

    float val = h * W2[lane];
    #pragma unroll
    for (int o = 16; o; o >>= 1) val += __shfl_xor_sync(0xffffffffu, val, o);

    if (lane == 0) {
        val += b2[0];
        float d0 = q[3*u + 0] - q[3*w + 0];
        float d1 = q[3*u + 1] - q[3*w + 1];
        float d2 = q[3*u + 2] - q[3*w + 2];
        float inv = rsqrtf(fmaf(d0, d0, fmaf(d1, d1, d2*d2)));
        float s = inv * val;
        out[3*warp + 0] = d0 * s;
        out[3*warp + 1] = d1 * s;
        out[3*warp + 2] = d2 * s;
    }
}

// ---------------------------------------------------------------------------
// Kernel D: relational forces — only same-molecule pairs (vvm*mm mask kills
// everything else; diagonal killed by nrm>0). One block (128 thr) per vertex.
// NOTE: smem loads use stride loops — previous rounds' bug was loading
// sWr[0..95] with only 64 threads, leaving Wr rows 21-31 uninitialized.
// ---------------------------------------------------------------------------
__global__ void rela_kernel(const float* __restrict__ m,
                            const float* __restrict__ q,
                            const float* __restrict__ Wr,
                            const float* __restrict__ br,
                            float* __restrict__ out) {
    __shared__ float sWr[H_DIM * 3];
    __shared__ float sbr[H_DIM];
    __shared__ float red[4][3];
    const int tid = threadIdx.x;
    for (int t = tid; t < H_DIM * 3; t += blockDim.x) sWr[t] = Wr[t];
    for (int t = tid; t < H_DIM;     t += blockDim.x) sbr[t] = br[t];
    __syncthreads();

    const int i  = blockIdx.x;
    const int mo = g_mol[i];
    const int s0 = g_off[mo], s1 = g_off[mo + 1];
    const float qi0 = q[3*i + 0], qi1 = q[3*i + 1], qi2 = q[3*i + 2];
    const float mi  = m[i];

    float a0 = 0.f, a1 = 0.f, a2 = 0.f;
    for (int s = s0 + tid; s < s1; s += blockDim.x) {
        const int j = g_sorted[s];
        float d0 = qi0 - q[3*j + 0];
        float d1 = qi1 - q[3*j + 1];
        float d2 = qi2 - q[3*j + 2];
        float n2 = fmaf(d0, d0, fmaf(d1, d1, d2*d2));
        if (n2 > 0.f) {
            float ss = 0.f;
            #pragma unroll
            for (int t = 0; t < H_DIM; t++) {
                float x = fmaf(sWr[3*t + 0], d0,
                          fmaf(sWr[3*t + 1], d1,
                          fmaf(sWr[3*t + 2], d2, sbr[t])));
                float sp = fmaxf(x, 0.f) + log1pf(__expf(-fabsf(x)));
                ss = fmaf(sp, sp, ss);
            }
            float y = rsqrtf(ss);                        // 1/delta_d
            float val = (y*y - y) * mi * m[j];
            float c = val * rsqrtf(n2);
            a0 = fmaf(d0, c, a0);
            a1 = fmaf(d1, c, a1);
            a2 = fmaf(d2, c, a2);
        }
    }

    // deterministic reduction: warp shuffle, then fixed 4-warp combine
    #pragma unroll
    for (int o = 16; o; o >>= 1) {
        a0 += __shfl_xor_sync(0xffffffffu, a0, o);
        a1 += __shfl_xor_sync(0xffffffffu, a1, o);
        a2 += __shfl_xor_sync(0xffffffffu, a2, o);
    }
    const int w = tid >> 5;
    if ((tid & 31) == 0) { red[w][0] = a0; red[w][1] = a1; red[w][2] = a2; }
    __syncthreads();
    if (tid == 0) {
        out[3*i + 0] += (red[0][0] + red[1][0]) + (red[2][0] + red[3][0]);
        out[3*i + 1] += (red[0][1] + red[1][1]) + (red[2][1] + red[3][1]);
        out[3*i + 2] += (red[0][2] + red[1][2]) + (red[2][2] + red[3][2]);
    }
}

// ---------------------------------------------------------------------------
extern "C" void kernel_launch(void* const* d_in, const int* in_sizes, int n_in,
                              void* d_out, int out_size) {
    const float* v    = (const float*)d_in[0];
    const float* e    = (const float*)d_in[1];
    const float* m    = (const float*)d_in[2];
    const float* q    = (const float*)d_in[3];
    const float* vew1 = (const float*)d_in[4];
    const float* vew2 = (const float*)d_in[5];
    const float* mvw  = (const float*)d_in[6];
    const float* W1   = (const float*)d_in[7];
    const float* W2   = (const float*)d_in[8];
    const float* b2   = (const float*)d_in[9];
    const float* Wr   = (const float*)d_in[10];
    const float* br   = (const float*)d_in[11];
    float* out = (float*)d_out;

    recover_kernel<<<512, 256>>>((const float4*)vew1, (const float4*)vew2,
                                 (const float4*)mvw);
    group_kernel<<<1, 256>>>();
    bond_kernel<<<(2 * N_E * 32) / 256, 256>>>(v, e, q, W1, W2, b2, out);
    rela_kernel<<<N_V, 128>>>(m, q, Wr, br, out);
}

// round 5
// speedup vs baseline: 4.2541x; 4.2541x over previous
#include <cuda_runtime.h>

#define N_V   2048
#define N_E   1024
#define N_MOL 64
#define V_DIM 128
#define E_DIM 64
#define H_DIM 32
#define FEAT  (2*V_DIM + E_DIM)   // 320
#define CAP   256                 // per-molecule member capacity (avg 32, max ~60)

// Scratch (static device globals — allocation-free per harness rules)
__device__ int g_src[N_E];
__device__ int g_dst[N_E];
__device__ int g_mol[N_V];

// ---------------------------------------------------------------------------
// Fast accurate softplus: softplus(x) = x/2 + ln2 + ln cosh(x/2).
// For |x|<1, 5-term even Taylor of ln cosh (abs err < 4e-7 at boundary,
// ~1e-10 typical) — FMA-pipe only, no MUFU. Exact path for |x|>=1 (rare).
// ---------------------------------------------------------------------------
__device__ __forceinline__ float softplus_fast(float x) {
    float ax = fabsf(x);
    if (ax < 1.0f) {
        float t = 0.5f * x;
        float u = t * t;
        float p = 2.1869489e-3f;            // 31/14175
        p = fmaf(p, u, -6.7460317e-3f);     // -17/2520
        p = fmaf(p, u,  2.2222222e-2f);     // 1/45
        p = fmaf(p, u, -8.3333333e-2f);     // -1/12
        p = fmaf(p, u,  0.5f);
        return fmaf(u, p, t + 0.69314718056f);
    }
    return fmaxf(x, 0.f) + log1pf(__expf(-ax));
}

// ---------------------------------------------------------------------------
// Kernel A: recover integer indices from one-hot matrices (16.8 MB scan).
// ---------------------------------------------------------------------------
__global__ void recover_kernel(const float4* __restrict__ vew1,
                               const float4* __restrict__ vew2,
                               const float4* __restrict__ mvw) {
    const int stride = gridDim.x * blockDim.x;
    const int n4 = (N_V * N_E) / 4;           // 524288
    for (int t = blockIdx.x * blockDim.x + threadIdx.x; t < n4; t += stride) {
        float4 a = vew1[t];
        float4 b = vew2[t];
        int i = t >> 8;
        int j = (t & 255) << 2;
        if (a.x != 0.f) g_src[j + 0] = i;
        if (a.y != 0.f) g_src[j + 1] = i;
        if (a.z != 0.f) g_src[j + 2] = i;
        if (a.w != 0.f) g_src[j + 3] = i;
        if (b.x != 0.f) g_dst[j + 0] = i;
        if (b.y != 0.f) g_dst[j + 1] = i;
        if (b.z != 0.f) g_dst[j + 2] = i;
        if (b.w != 0.f) g_dst[j + 3] = i;
    }
    const int nm4 = (N_MOL * N_V) / 4;        // 32768
    for (int t = blockIdx.x * blockDim.x + threadIdx.x; t < nm4; t += stride) {
        float4 a = mvw[t];
        int g = t >> 9;
        int i = (t & 511) << 2;
        if (a.x != 0.f) g_mol[i + 0] = g;
        if (a.y != 0.f) g_mol[i + 1] = g;
        if (a.z != 0.f) g_mol[i + 2] = g;
        if (a.w != 0.f) g_mol[i + 3] = g;
    }
}

// ---------------------------------------------------------------------------
// Kernel B: bond forces, register-tiled. One warp per output row k.
// Lane L owns feature slots c = 32k+L (coalesced loads of v/e and of every
// W1 row); 32 partial accumulators per lane; padded-smem transpose reduce.
// ---------------------------------------------------------------------------
__global__ void bond_kernel(const float* __restrict__ v,
                            const float* __restrict__ e,
                            const float* __restrict__ q,
                            const float* __restrict__ W1,
                            const float* __restrict__ W2,
                            const float* __restrict__ b2,
                            float* __restrict__ out) {
    __shared__ float sred[8][32 * 33];        // per-warp 32x32 padded transpose
    const int warp = (blockIdx.x * blockDim.x + threadIdx.x) >> 5;
    const int wl   = threadIdx.x >> 5;
    const int lane = threadIdx.x & 31;
    if (warp >= 2 * N_E) return;
    const int er = (warp < N_E) ? warp : warp - N_E;
    int u, w;
    if (warp < N_E) { u = g_src[er]; w = g_dst[er]; }
    else            { u = g_dst[er]; w = g_src[er]; }

    const float* __restrict__ vu = v + u * V_DIM;
    const float* __restrict__ vw = v + w * V_DIM;
    const float* __restrict__ ee = e + er * E_DIM;

    // lane's feature values across the 10 c-chunks (all coalesced)
    float f[10];
    #pragma unroll
    for (int k = 0; k < 4; k++) f[k] = vu[32 * k + lane];
    f[4] = ee[lane];
    f[5] = ee[32 + lane];
    #pragma unroll
    for (int k = 0; k < 4; k++) f[6 + k] = vw[32 * k + lane];

    float acc[32];
    #pragma unroll
    for (int t = 0; t < 32; t++) acc[t] = 0.f;

    #pragma unroll
    for (int k = 0; k < 10; k++) {
        const float* __restrict__ Wp = W1 + 32 * k + lane;  // W1[t][32k+lane]
        float fk = f[k];
        #pragma unroll
        for (int t = 0; t < 32; t++)
            acc[t] = fmaf(fk, Wp[t * FEAT], acc[t]);
    }

    // transpose-reduce: lane stores its 32 partials, then sums column `lane`
    float* sr = sred[wl];
    #pragma unroll
    for (int t = 0; t < 32; t++) sr[lane * 33 + t] = acc[t];
    __syncwarp();
    float h = 0.f;
    #pragma unroll
    for (int l = 0; l < 32; l++) h += sr[l * 33 + lane];
    // lane holds h_{t=lane}
    h = fmaxf(h, 0.f);
    float val = h * W2[lane];
    #pragma unroll
    for (int o = 16; o; o >>= 1) val += __shfl_xor_sync(0xffffffffu, val, o);

    if (lane == 0) {
        val += b2[0];
        float d0 = q[3*u + 0] - q[3*w + 0];
        float d1 = q[3*u + 1] - q[3*w + 1];
        float d2 = q[3*u + 2] - q[3*w + 2];
        float s = rsqrtf(fmaf(d0, d0, fmaf(d1, d1, d2 * d2))) * val;
        out[3*warp + 0] = d0 * s;
        out[3*warp + 1] = d1 * s;
        out[3*warp + 2] = d2 * s;
    }
}

// ---------------------------------------------------------------------------
// Kernel D: relational forces. 2 blocks per molecule (parity-split members).
// Each block deterministically compacts its molecule's members from g_mol
// via ordered ballots, then warp-per-member, lanes over partners.
// ---------------------------------------------------------------------------
__global__ void rela_kernel(const float* __restrict__ m,
                            const float* __restrict__ q,
                            const float* __restrict__ Wr,
                            const float* __restrict__ br,
                            float* __restrict__ out) {
    __shared__ int   midx[CAP];
    __shared__ float sqx[CAP], sqy[CAP], sqz[CAP], smm[CAP];
    __shared__ float sWr0[H_DIM], sWr1[H_DIM], sWr2[H_DIM], sbr[H_DIM];
    __shared__ int   wcnt[8];
    __shared__ int   s_base;

    const int tid  = threadIdx.x;
    const int lane = tid & 31;
    const int wl   = tid >> 5;
    const int mo   = blockIdx.x >> 1;
    const int par  = blockIdx.x & 1;

    if (tid < H_DIM) {
        sWr0[tid] = Wr[3*tid + 0];
        sWr1[tid] = Wr[3*tid + 1];
        sWr2[tid] = Wr[3*tid + 2];
        sbr[tid]  = br[tid];
    }
    if (tid == 0) s_base = 0;
    __syncthreads();

    // deterministic ordered compaction of molecule members
    for (int base = 0; base < N_V; base += 256) {
        const int t = base + tid;
        const bool hit = (g_mol[t] == mo);
        const unsigned msk = __ballot_sync(0xffffffffu, hit);
        if (lane == 0) wcnt[wl] = __popc(msk);
        __syncthreads();
        int woff = s_base;
        #pragma unroll
        for (int j = 0; j < 8; j++) if (j < wl) woff += wcnt[j];
        if (hit) {
            int p = woff + __popc(msk & ((1u << lane) - 1u));
            if (p < CAP) {
                midx[p] = t;
                sqx[p] = q[3*t + 0];
                sqy[p] = q[3*t + 1];
                sqz[p] = q[3*t + 2];
                smm[p] = m[t];
            }
        }
        __syncthreads();
        if (tid == 0) {
            int s = 0;
            #pragma unroll
            for (int j = 0; j < 8; j++) s += wcnt[j];
            s_base += s;
        }
        __syncthreads();
    }
    int size = s_base;
    if (size > CAP) size = CAP;

    // warp-per-member (this block handles members with index parity `par`)
    for (int s = par + 2 * wl; s < size; s += 16) {
        const float qix = sqx[s], qiy = sqy[s], qiz = sqz[s], mi = smm[s];
        float a0 = 0.f, a1 = 0.f, a2 = 0.f;
        for (int t = lane; t < size; t += 32) {
            float d0 = qix - sqx[t];
            float d1 = qiy - sqy[t];
            float d2 = qiz - sqz[t];
            float n2 = fmaf(d0, d0, fmaf(d1, d1, d2 * d2));
            if (n2 > 0.f) {
                float ss = 0.f;
                #pragma unroll
                for (int h = 0; h < H_DIM; h++) {
                    float x = fmaf(sWr0[h], d0,
                              fmaf(sWr1[h], d1,
                              fmaf(sWr2[h], d2, sbr[h])));
                    float sp = softplus_fast(x);
                    ss = fmaf(sp, sp, ss);
                }
                float y = rsqrtf(ss);                      // 1/delta_d
                float c = (y * y - y) * mi * smm[t] * rsqrtf(n2);
                a0 = fmaf(d0, c, a0);
                a1 = fmaf(d1, c, a1);
                a2 = fmaf(d2, c, a2);
            }
        }
        #pragma unroll
        for (int o = 16; o; o >>= 1) {
            a0 += __shfl_xor_sync(0xffffffffu, a0, o);
            a1 += __shfl_xor_sync(0xffffffffu, a1, o);
            a2 += __shfl_xor_sync(0xffffffffu, a2, o);
        }
        if (lane == 0) {
            const int i = midx[s];
            out[3*i + 0] += a0;
            out[3*i + 1] += a1;
            out[3*i + 2] += a2;
        }
    }
}

// ---------------------------------------------------------------------------
extern "C" void kernel_launch(void* const* d_in, const int* in_sizes, int n_in,
                              void* d_out, int out_size) {
    const float* v    = (const float*)d_in[0];
    const float* e    = (const float*)d_in[1];
    const float* m    = (const float*)d_in[2];
    const float* q    = (const float*)d_in[3];
    const float* vew1 = (const float*)d_in[4];
    const float* vew2 = (const float*)d_in[5];
    const float* mvw  = (const float*)d_in[6];
    const float* W1   = (const float*)d_in[7];
    const float* W2   = (const float*)d_in[8];
    const float* b2   = (const float*)d_in[9];
    const float* Wr   = (const float*)d_in[10];
    const float* br   = (const float*)d_in[11];
    float* out = (float*)d_out;

    recover_kernel<<<2048, 256>>>((const float4*)vew1, (const float4*)vew2,
                                  (const float4*)mvw);
    bond_kernel<<<(2 * N_E * 32) / 256, 256>>>(v, e, q, W1, W2, b2, out);
    rela_kernel<<<2 * N_MOL, 256>>>(m, q, Wr, br, out);
}

// round 8
// speedup vs baseline: 4.4638x; 1.0493x over previous
#include <cuda_runtime.h>

#define N_V   2048
#define N_E   1024
#define N_MOL 64
#define V_DIM 128
#define E_DIM 64
#define H_DIM 32
#define FEAT  (2*V_DIM + E_DIM)   // 320
#define CAP   256                 // per-molecule member capacity (avg 32)

// Scratch (static device globals — allocation-free per harness rules)
__device__ int   g_src[N_E];
__device__ int   g_dst[N_E];
__device__ float g_rela[N_V * 3];

// ---------------------------------------------------------------------------
// Fast accurate softplus: softplus(x) = x/2 + ln2 + ln cosh(x/2).
// |x|<1: 5-term even Taylor of ln cosh (abs err < 4e-7 at boundary) — FMA
// pipe only. Exact path for |x|>=1 (rare; inputs have sigma ~0.13).
// ---------------------------------------------------------------------------
__device__ __forceinline__ float softplus_fast(float x) {
    float ax = fabsf(x);
    if (ax < 1.0f) {
        float t = 0.5f * x;
        float u = t * t;
        float p = 2.1869489e-3f;
        p = fmaf(p, u, -6.7460317e-3f);
        p = fmaf(p, u,  2.2222222e-2f);
        p = fmaf(p, u, -8.3333333e-2f);
        p = fmaf(p, u,  0.5f);
        return fmaf(u, p, t + 0.69314718056f);
    }
    return fmaxf(x, 0.f) + log1pf(__expf(-ax));
}

// ---------------------------------------------------------------------------
// Kernel A: recover src/dst from one-hot vew1/vew2 (16.8 MB scan).
// 512 blocks x 256 threads; each thread front-batches 4 float4 per matrix
// (MLP=8) so DRAM latency is fully hidden per the B300 LDG model.
// ---------------------------------------------------------------------------
__global__ void recover_kernel(const float4* __restrict__ vew1,
                               const float4* __restrict__ vew2) {
    const int gtid = blockIdx.x * 256 + threadIdx.x;   // 131072 threads
    float4 a[4], b[4];
    #pragma unroll
    for (int r = 0; r < 4; r++) a[r] = vew1[r * 131072 + gtid];
    #pragma unroll
    for (int r = 0; r < 4; r++) b[r] = vew2[r * 131072 + gtid];
    #pragma unroll
    for (int r = 0; r < 4; r++) {
        const int idx = r * 131072 + gtid;
        const int i = idx >> 8;            // row (vertex)
        const int j = (idx & 255) << 2;    // edge base
        if (a[r].x != 0.f) g_src[j + 0] = i;
        if (a[r].y != 0.f) g_src[j + 1] = i;
        if (a[r].z != 0.f) g_src[j + 2] = i;
        if (a[r].w != 0.f) g_src[j + 3] = i;
        if (b[r].x != 0.f) g_dst[j + 0] = i;
        if (b[r].y != 0.f) g_dst[j + 1] = i;
        if (b[r].z != 0.f) g_dst[j + 2] = i;
        if (b[r].w != 0.f) g_dst[j + 3] = i;
    }
}

// ---------------------------------------------------------------------------
// Kernel D: relational forces -> g_rela. 2 blocks per molecule (parity-split
// members). Each block deterministically compacts its molecule's members
// directly from its mvw row via ordered ballots (no index scratch needed),
// then warp-per-member, lanes over partners. Independent of recover/bond.
// ---------------------------------------------------------------------------
__global__ void rela_kernel(const float* __restrict__ mvw,
                            const float* __restrict__ m,
                            const float* __restrict__ q,
                            const float* __restrict__ Wr,
                            const float* __restrict__ br) {
    __shared__ int   midx[CAP];
    __shared__ float sqx[CAP], sqy[CAP], sqz[CAP], smm[CAP];
    __shared__ float sWr0[H_DIM], sWr1[H_DIM], sWr2[H_DIM], sbr[H_DIM];
    __shared__ int   wcnt[8];
    __shared__ int   s_base;

    const int tid  = threadIdx.x;
    const int lane = tid & 31;
    const int wl   = tid >> 5;
    const int mo   = blockIdx.x >> 1;
    const int par  = blockIdx.x & 1;

    if (tid < H_DIM) {
        sWr0[tid] = Wr[3*tid + 0];
        sWr1[tid] = Wr[3*tid + 1];
        sWr2[tid] = Wr[3*tid + 2];
        sbr[tid]  = br[tid];
    }
    if (tid == 0) s_base = 0;
    __syncthreads();

    // deterministic ordered compaction of this molecule's members from mvw row
    const float* __restrict__ mrow = mvw + mo * N_V;
    for (int base = 0; base < N_V; base += 256) {
        const int t = base + tid;
        const bool hit = (mrow[t] != 0.f);
        const unsigned msk = __ballot_sync(0xffffffffu, hit);
        if (lane == 0) wcnt[wl] = __popc(msk);
        __syncthreads();
        int woff = s_base;
        #pragma unroll
        for (int j = 0; j < 8; j++) if (j < wl) woff += wcnt[j];
        if (hit) {
            int p = woff + __popc(msk & ((1u << lane) - 1u));
            if (p < CAP) {
                midx[p] = t;
                sqx[p] = q[3*t + 0];
                sqy[p] = q[3*t + 1];
                sqz[p] = q[3*t + 2];
                smm[p] = m[t];
            }
        }
        __syncthreads();
        if (tid == 0) {
            int s = 0;
            #pragma unroll
            for (int j = 0; j < 8; j++) s += wcnt[j];
            s_base += s;
        }
        __syncthreads();
    }
    int size = s_base;
    if (size > CAP) size = CAP;

    // warp-per-member; this block handles members with index parity `par`
    for (int s = par + 2 * wl; s < size; s += 16) {
        const float qix = sqx[s], qiy = sqy[s], qiz = sqz[s], mi = smm[s];
        float a0 = 0.f, a1 = 0.f, a2 = 0.f;
        for (int t = lane; t < size; t += 32) {
            float d0 = qix - sqx[t];
            float d1 = qiy - sqy[t];
            float d2 = qiz - sqz[t];
            float n2 = fmaf(d0, d0, fmaf(d1, d1, d2 * d2));
            if (n2 > 0.f) {
                float ss = 0.f;
                #pragma unroll
                for (int h = 0; h < H_DIM; h++) {
                    float x = fmaf(sWr0[h], d0,
                              fmaf(sWr1[h], d1,
                              fmaf(sWr2[h], d2, sbr[h])));
                    float sp = softplus_fast(x);
                    ss = fmaf(sp, sp, ss);
                }
                float y = rsqrtf(ss);                   // 1/delta_d
                float c = (y * y - y) * mi * smm[t] * rsqrtf(n2);
                a0 = fmaf(d0, c, a0);
                a1 = fmaf(d1, c, a1);
                a2 = fmaf(d2, c, a2);
            }
        }
        #pragma unroll
        for (int o = 16; o; o >>= 1) {
            a0 += __shfl_xor_sync(0xffffffffu, a0, o);
            a1 += __shfl_xor_sync(0xffffffffu, a1, o);
            a2 += __shfl_xor_sync(0xffffffffu, a2, o);
        }
        if (lane == 0) {
            const int i = midx[s];          // each vertex written exactly once
            g_rela[3*i + 0] = a0;
            g_rela[3*i + 1] = a1;
            g_rela[3*i + 2] = a2;
        }
    }
}

// ---------------------------------------------------------------------------
// Kernel B: bond forces + final combine. One warp per output row k of [2*N_E].
// W1 staged in smem (40 KB); lane L owns feature slots c = 32k+L; 32 partial
// accumulators reduced with a 31-shuffle log-compaction butterfly so that
// lane t ends holding h_t. out[k] = f_bond[k] + g_rela[k].
// ---------------------------------------------------------------------------
__global__ void bond_kernel(const float* __restrict__ v,
                            const float* __restrict__ e,
                            const float* __restrict__ q,
                            const float* __restrict__ W1,
                            const float* __restrict__ W2,
                            const float* __restrict__ b2,
                            float* __restrict__ out) {
    __shared__ float sW1[H_DIM * FEAT];               // 40 KB, [t][c]
    const int tid = threadIdx.x;
    for (int t = tid; t < (H_DIM * FEAT) / 4; t += 256)
        ((float4*)sW1)[t] = ((const float4*)W1)[t];
    __syncthreads();

    const int warp = (blockIdx.x * blockDim.x + tid) >> 5;
    const int lane = tid & 31;
    if (warp >= 2 * N_E) return;
    const int er = (warp < N_E) ? warp : warp - N_E;
    int u, w;
    if (warp < N_E) { u = g_src[er]; w = g_dst[er]; }
    else            { u = g_dst[er]; w = g_src[er]; }

    const float* __restrict__ vu = v + u * V_DIM;
    const float* __restrict__ vw = v + w * V_DIM;
    const float* __restrict__ ee = e + er * E_DIM;

    // lane's feature values across the 10 c-chunks (all coalesced)
    float f[10];
    #pragma unroll
    for (int k = 0; k < 4; k++) f[k] = vu[32 * k + lane];
    f[4] = ee[lane];
    f[5] = ee[32 + lane];
    #pragma unroll
    for (int k = 0; k < 4; k++) f[6 + k] = vw[32 * k + lane];

    float acc[32];
    #pragma unroll
    for (int t = 0; t < 32; t++) acc[t] = 0.f;

    #pragma unroll
    for (int k = 0; k < 10; k++) {
        const float* __restrict__ Wp = sW1 + 32 * k + lane;  // conflict-free
        const float fk = f[k];
        #pragma unroll
        for (int t = 0; t < 32; t++)
            acc[t] = fmaf(fk, Wp[t * FEAT], acc[t]);
    }

    // log-compaction butterfly: after step s, acc[k] holds the partial for
    // hidden index (k << (s+1)) | (lane & ((2<<s)-1)); ends with acc[0]=h[lane]
    #pragma unroll
    for (int s = 0; s < 5; s++) {
        const int o = 1 << s;
        const int n = 16 >> s;
        #pragma unroll
        for (int k = 0; k < 16; k++) {
            if (k < n) {
                float give = (lane & o) ? acc[2*k]     : acc[2*k + 1];
                float keep = (lane & o) ? acc[2*k + 1] : acc[2*k];
                acc[k] = keep + __shfl_xor_sync(0xffffffffu, give, o);
            }
        }
    }
    float h = fmaxf(acc[0], 0.f);                     // h_{t=lane}

    float val = h * W2[lane];
    #pragma unroll
    for (int o = 16; o; o >>= 1) val += __shfl_xor_sync(0xffffffffu, val, o);

    if (lane == 0) {
        val += b2[0];
        float d0 = q[3*u + 0] - q[3*w + 0];
        float d1 = q[3*u + 1] - q[3*w + 1];
        float d2 = q[3*u + 2] - q[3*w + 2];
        float s = rsqrtf(fmaf(d0, d0, fmaf(d1, d1, d2 * d2))) * val;
        out[3*warp + 0] = fmaf(d0, s, g_rela[3*warp + 0]);
        out[3*warp + 1] = fmaf(d1, s, g_rela[3*warp + 1]);
        out[3*warp + 2] = fmaf(d2, s, g_rela[3*warp + 2]);
    }
}

// ---------------------------------------------------------------------------
extern "C" void kernel_launch(void* const* d_in, const int* in_sizes, int n_in,
                              void* d_out, int out_size) {
    const float* v    = (const float*)d_in[0];
    const float* e    = (const float*)d_in[1];
    const float* m    = (const float*)d_in[2];
    const float* q    = (const float*)d_in[3];
    const float* vew1 = (const float*)d_in[4];
    const float* vew2 = (const float*)d_in[5];
    const float* mvw  = (const float*)d_in[6];
    const float* W1   = (const float*)d_in[7];
    const float* W2   = (const float*)d_in[8];
    const float* b2   = (const float*)d_in[9];
    const float* Wr   = (const float*)d_in[10];
    const float* br   = (const float*)d_in[11];
    float* out = (float*)d_out;

    recover_kernel<<<512, 256>>>((const float4*)vew1, (const float4*)vew2);
    rela_kernel<<<2 * N_MOL, 256>>>(mvw, m, q, Wr, br);
    bond_kernel<<<(2 * N_E * 32) / 256, 256>>>(v, e, q, W1, W2, b2, out);
}